// round 1
// baseline (speedup 1.0000x reference)
#include <cuda_runtime.h>
#include <math.h>

#define Dm   512
#define Hh   8
#define DKh  64
#define FFm  2048
#define Vv   10000
#define Ll   6
#define Bb   8
#define Ss   512
#define MR   (Bb*Ss)   // 4096 token rows

// ---------------- scratch (device globals; no allocation allowed) ----------
__device__ float g_x [MR*Dm];    // encoder activations / enc_out
__device__ float g_y [MR*Dm];    // decoder activations
__device__ float g_q [MR*Dm];
__device__ float g_k [MR*Dm];
__device__ float g_v [MR*Dm];
__device__ float g_t [MR*Dm];    // attention output (pre O-proj)
__device__ float g_a [MR*Dm];    // sublayer result before residual+LN
__device__ float g_ff[MR*FFm];   // FFN hidden

// ---------------- embedding + sinusoidal positional encoding ---------------
__global__ void embed_kernel(const int* __restrict__ tok,
                             const float* __restrict__ emb,
                             float* __restrict__ x)
{
    int idx = blockIdx.x * blockDim.x + threadIdx.x;
    if (idx >= MR * Dm) return;
    int d  = idx & (Dm - 1);
    int bs = idx >> 9;            // b*S + s
    int s  = bs & (Ss - 1);
    int t  = tok[bs];
    // div = exp((2i) * (-ln(10000)/D)), computed in fp32 like numpy
    const float c = -0.017988946039015985f;  // -ln(10000)/512
    int i2 = d & ~1;
    float f   = expf((float)i2 * c);
    float ang = (float)s * f;
    float pe  = (d & 1) ? cosf(ang) : sinf(ang);
    x[idx] = emb[t * Dm + d] + pe;
}

// ---------------- generic SGEMM: C = A[M,K] @ W[K,N] + bias, opt ReLU ------
// BM=BN=128, BK=8, 256 threads, 8x8 per thread. M%128==0, K%8==0 guaranteed.
__global__ void sgemm_kernel(const float* __restrict__ A,
                             const float* __restrict__ W,
                             const float* __restrict__ bias,
                             float* __restrict__ C,
                             int M, int N, int K, int relu)
{
    __shared__ float As[8][128];
    __shared__ float Ws[8][128];

    int tid = threadIdx.x;
    int bx = blockIdx.x, by = blockIdx.y;
    int tx = tid & 15, ty = tid >> 4;

    int aRow = tid >> 1;            // 0..127
    int aCol = (tid & 1) << 2;      // 0 or 4
    int wRow = tid >> 5;            // 0..7
    int wCol = (tid & 31) << 2;     // 0..124

    int rowBase = by * 128;
    int colBase = bx * 128;

    float acc[8][8];
    #pragma unroll
    for (int i = 0; i < 8; i++)
        #pragma unroll
        for (int j = 0; j < 8; j++) acc[i][j] = 0.f;

    for (int k0 = 0; k0 < K; k0 += 8) {
        float4 a4 = *reinterpret_cast<const float4*>(&A[(rowBase + aRow) * K + k0 + aCol]);
        As[aCol + 0][aRow] = a4.x;
        As[aCol + 1][aRow] = a4.y;
        As[aCol + 2][aRow] = a4.z;
        As[aCol + 3][aRow] = a4.w;

        int wc = colBase + wCol;
        if (wc + 4 <= N) {
            float4 w4 = *reinterpret_cast<const float4*>(&W[(k0 + wRow) * N + wc]);
            Ws[wRow][wCol + 0] = w4.x;
            Ws[wRow][wCol + 1] = w4.y;
            Ws[wRow][wCol + 2] = w4.z;
            Ws[wRow][wCol + 3] = w4.w;
        } else {
            #pragma unroll
            for (int j = 0; j < 4; j++)
                Ws[wRow][wCol + j] = (wc + j < N) ? W[(k0 + wRow) * N + wc + j] : 0.f;
        }
        __syncthreads();

        #pragma unroll
        for (int kk = 0; kk < 8; kk++) {
            float ar[8], wr[8];
            #pragma unroll
            for (int i = 0; i < 8; i++) ar[i] = As[kk][ty * 8 + i];
            #pragma unroll
            for (int j = 0; j < 8; j++) wr[j] = Ws[kk][tx * 8 + j];
            #pragma unroll
            for (int i = 0; i < 8; i++)
                #pragma unroll
                for (int j = 0; j < 8; j++) acc[i][j] += ar[i] * wr[j];
        }
        __syncthreads();
    }

    #pragma unroll
    for (int i = 0; i < 8; i++) {
        int r = rowBase + ty * 8 + i;
        #pragma unroll
        for (int j = 0; j < 8; j++) {
            int c = colBase + tx * 8 + j;
            if (c < N) {
                float v = acc[i][j] + bias[c];
                if (relu) v = fmaxf(v, 0.f);
                C[r * N + c] = v;
            }
        }
    }
}

// ---------------- fused attention ------------------------------------------
// grid (S/8, H, B), 128 threads. 8 q-rows per block, full score row in smem.
// mask_tok != causal mode: key k valid iff mask_tok[b*S+k] != 0.
__global__ void attn_kernel(const float* __restrict__ Q,
                            const float* __restrict__ Kp,
                            const float* __restrict__ Vp,
                            float* __restrict__ O,
                            const int* __restrict__ mask_tok,
                            int causal)
{
    int q0 = blockIdx.x * 8;
    int h  = blockIdx.y;
    int b  = blockIdx.z;
    int tid = threadIdx.x;

    __shared__ float sQ[8][64];
    __shared__ float sT[32][65];     // padded to kill bank conflicts
    __shared__ float sS[8][512];

    // load Q tile
    for (int i = tid; i < 8 * 64; i += 128) {
        int r = i >> 6, c = i & 63;
        sQ[r][c] = Q[((b * Ss + q0 + r) * Dm) + h * 64 + c];
    }

    // scores
    for (int kt = 0; kt < 16; kt++) {
        __syncthreads();
        for (int i = tid; i < 32 * 64; i += 128) {
            int r = i >> 6, c = i & 63;
            sT[r][c] = Kp[((b * Ss + kt * 32 + r) * Dm) + h * 64 + c];
        }
        __syncthreads();
        #pragma unroll
        for (int ii = 0; ii < 2; ii++) {
            int e = tid + 128 * ii;
            int kr = e & 31, qr = e >> 5;
            float s = 0.f;
            #pragma unroll
            for (int c = 0; c < 64; c++) s += sQ[qr][c] * sT[kr][c];
            int kg = kt * 32 + kr;
            bool valid = causal ? (kg <= q0 + qr) : (mask_tok[b * Ss + kg] != 0);
            sS[qr][kg] = valid ? s * 0.125f : -INFINITY;
        }
    }
    __syncthreads();

    // softmax: warp handles 2 rows
    int warp = tid >> 5, lane = tid & 31;
    for (int r = warp * 2; r < warp * 2 + 2; r++) {
        float m = -INFINITY;
        for (int k = lane; k < 512; k += 32) m = fmaxf(m, sS[r][k]);
        #pragma unroll
        for (int o = 16; o; o >>= 1) m = fmaxf(m, __shfl_xor_sync(0xffffffff, m, o));
        float ssum = 0.f;
        for (int k = lane; k < 512; k += 32) {
            float e = expf(sS[r][k] - m);
            sS[r][k] = e;
            ssum += e;
        }
        #pragma unroll
        for (int o = 16; o; o >>= 1) ssum += __shfl_xor_sync(0xffffffff, ssum, o);
        float inv = (ssum > 0.f) ? (1.f / ssum) : 0.f;
        for (int k = lane; k < 512; k += 32) sS[r][k] *= inv;
    }

    // PV
    float acc[4] = {0.f, 0.f, 0.f, 0.f};
    for (int vt = 0; vt < 16; vt++) {
        __syncthreads();
        for (int i = tid; i < 32 * 64; i += 128) {
            int r = i >> 6, c = i & 63;
            sT[r][c] = Vp[((b * Ss + vt * 32 + r) * Dm) + h * 64 + c];
        }
        __syncthreads();
        #pragma unroll
        for (int ii = 0; ii < 4; ii++) {
            int e = tid + 128 * ii;
            int qr = e >> 6, c = e & 63;
            float a = acc[ii];
            #pragma unroll
            for (int kr = 0; kr < 32; kr++) a += sS[qr][vt * 32 + kr] * sT[kr][c];
            acc[ii] = a;
        }
    }
    #pragma unroll
    for (int ii = 0; ii < 4; ii++) {
        int e = tid + 128 * ii;
        int qr = e >> 6, c = e & 63;
        O[((b * Ss + q0 + qr) * Dm) + h * 64 + c] = acc[ii];
    }
}

// ---------------- residual + LayerNorm (in-place on x) ---------------------
__global__ void ln_res_kernel(float* __restrict__ x,
                              const float* __restrict__ a,
                              const float* __restrict__ g,
                              const float* __restrict__ b)
{
    int row = blockIdx.x;
    int tid = threadIdx.x;   // 256
    __shared__ float red[256];

    float v0 = x[row * Dm + tid]       + a[row * Dm + tid];
    float v1 = x[row * Dm + tid + 256] + a[row * Dm + tid + 256];

    red[tid] = v0 + v1;
    __syncthreads();
    for (int st = 128; st > 0; st >>= 1) {
        if (tid < st) red[tid] += red[tid + st];
        __syncthreads();
    }
    float mu = red[0] * (1.f / 512.f);
    __syncthreads();

    float d0 = v0 - mu, d1 = v1 - mu;
    red[tid] = d0 * d0 + d1 * d1;
    __syncthreads();
    for (int st = 128; st > 0; st >>= 1) {
        if (tid < st) red[tid] += red[tid + st];
        __syncthreads();
    }
    float rs = rsqrtf(red[0] * (1.f / 512.f) + 1e-5f);

    x[row * Dm + tid]       = d0 * rs * g[tid]       + b[tid];
    x[row * Dm + tid + 256] = d1 * rs * g[tid + 256] + b[tid + 256];
}

// ---------------- host orchestration ---------------------------------------
static inline void gemm(const float* A, const float* W, const float* bias,
                        float* C, int M, int N, int K, int relu)
{
    dim3 grid((N + 127) / 128, (M + 127) / 128);
    sgemm_kernel<<<grid, 256>>>(A, W, bias, C, M, N, K, relu);
}

extern "C" void kernel_launch(void* const* d_in, const int* in_sizes, int n_in,
                              void* d_out, int out_size)
{
    const int*   src       = (const int*)  d_in[0];
    const int*   tgt       = (const int*)  d_in[1];
    const float* src_emb   = (const float*)d_in[2];
    const float* tgt_emb   = (const float*)d_in[3];
    const float* enc_w     = (const float*)d_in[4];
    const float* enc_b     = (const float*)d_in[5];
    const float* enc_ff1_w = (const float*)d_in[6];
    const float* enc_ff1_b = (const float*)d_in[7];
    const float* enc_ff2_w = (const float*)d_in[8];
    const float* enc_ff2_b = (const float*)d_in[9];
    const float* enc_ln_g  = (const float*)d_in[10];
    const float* enc_ln_b  = (const float*)d_in[11];
    const float* dec_sa_w  = (const float*)d_in[12];
    const float* dec_sa_b  = (const float*)d_in[13];
    const float* dec_ca_w  = (const float*)d_in[14];
    const float* dec_ca_b  = (const float*)d_in[15];
    const float* dec_ff1_w = (const float*)d_in[16];
    const float* dec_ff1_b = (const float*)d_in[17];
    const float* dec_ff2_w = (const float*)d_in[18];
    const float* dec_ff2_b = (const float*)d_in[19];
    const float* dec_ln_g  = (const float*)d_in[20];
    const float* dec_ln_b  = (const float*)d_in[21];
    const float* out_w     = (const float*)d_in[22];
    const float* out_b     = (const float*)d_in[23];
    float* out = (float*)d_out;

    float *x, *y, *q, *k, *v, *t, *a, *ff;
    cudaGetSymbolAddress((void**)&x,  g_x);
    cudaGetSymbolAddress((void**)&y,  g_y);
    cudaGetSymbolAddress((void**)&q,  g_q);
    cudaGetSymbolAddress((void**)&k,  g_k);
    cudaGetSymbolAddress((void**)&v,  g_v);
    cudaGetSymbolAddress((void**)&t,  g_t);
    cudaGetSymbolAddress((void**)&a,  g_a);
    cudaGetSymbolAddress((void**)&ff, g_ff);

    const int DD = Dm * Dm;
    dim3 attn_grid(Ss / 8, Hh, Bb);

    // ===================== encoder =====================
    embed_kernel<<<(MR * Dm + 255) / 256, 256>>>(src, src_emb, x);
    for (int l = 0; l < Ll; l++) {
        const float* w = enc_w + (size_t)l * 4 * DD;
        const float* bb = enc_b + (size_t)l * 4 * Dm;
        gemm(x, w + 0 * DD, bb + 0 * Dm, q, MR, Dm, Dm, 0);
        gemm(x, w + 1 * DD, bb + 1 * Dm, k, MR, Dm, Dm, 0);
        gemm(x, w + 2 * DD, bb + 2 * Dm, v, MR, Dm, Dm, 0);
        attn_kernel<<<attn_grid, 128>>>(q, k, v, t, src, 0);
        gemm(t, w + 3 * DD, bb + 3 * Dm, a, MR, Dm, Dm, 0);
        ln_res_kernel<<<MR, 256>>>(x, a, enc_ln_g + (size_t)(l * 2 + 0) * Dm,
                                         enc_ln_b + (size_t)(l * 2 + 0) * Dm);
        gemm(x, enc_ff1_w + (size_t)l * Dm * FFm, enc_ff1_b + (size_t)l * FFm,
             ff, MR, FFm, Dm, 1);
        gemm(ff, enc_ff2_w + (size_t)l * FFm * Dm, enc_ff2_b + (size_t)l * Dm,
             a, MR, Dm, FFm, 0);
        ln_res_kernel<<<MR, 256>>>(x, a, enc_ln_g + (size_t)(l * 2 + 1) * Dm,
                                         enc_ln_b + (size_t)(l * 2 + 1) * Dm);
    }

    // ===================== decoder =====================
    embed_kernel<<<(MR * Dm + 255) / 256, 256>>>(tgt, tgt_emb, y);
    for (int l = 0; l < Ll; l++) {
        // self-attention (causal)
        const float* w = dec_sa_w + (size_t)l * 4 * DD;
        const float* bb = dec_sa_b + (size_t)l * 4 * Dm;
        gemm(y, w + 0 * DD, bb + 0 * Dm, q, MR, Dm, Dm, 0);
        gemm(y, w + 1 * DD, bb + 1 * Dm, k, MR, Dm, Dm, 0);
        gemm(y, w + 2 * DD, bb + 2 * Dm, v, MR, Dm, Dm, 0);
        attn_kernel<<<attn_grid, 128>>>(q, k, v, t, (const int*)0, 1);
        gemm(t, w + 3 * DD, bb + 3 * Dm, a, MR, Dm, Dm, 0);
        ln_res_kernel<<<MR, 256>>>(y, a, dec_ln_g + (size_t)(l * 3 + 0) * Dm,
                                         dec_ln_b + (size_t)(l * 3 + 0) * Dm);
        // cross-attention (K,V from enc_out; mask from tgt tokens, per reference)
        const float* wc = dec_ca_w + (size_t)l * 4 * DD;
        const float* bc = dec_ca_b + (size_t)l * 4 * Dm;
        gemm(y, wc + 0 * DD, bc + 0 * Dm, q, MR, Dm, Dm, 0);
        gemm(x, wc + 1 * DD, bc + 1 * Dm, k, MR, Dm, Dm, 0);
        gemm(x, wc + 2 * DD, bc + 2 * Dm, v, MR, Dm, Dm, 0);
        attn_kernel<<<attn_grid, 128>>>(q, k, v, t, tgt, 0);
        gemm(t, wc + 3 * DD, bc + 3 * Dm, a, MR, Dm, Dm, 0);
        ln_res_kernel<<<MR, 256>>>(y, a, dec_ln_g + (size_t)(l * 3 + 1) * Dm,
                                         dec_ln_b + (size_t)(l * 3 + 1) * Dm);
        // FFN
        gemm(y, dec_ff1_w + (size_t)l * Dm * FFm, dec_ff1_b + (size_t)l * FFm,
             ff, MR, FFm, Dm, 1);
        gemm(ff, dec_ff2_w + (size_t)l * FFm * Dm, dec_ff2_b + (size_t)l * Dm,
             a, MR, Dm, FFm, 0);
        ln_res_kernel<<<MR, 256>>>(y, a, dec_ln_g + (size_t)(l * 3 + 2) * Dm,
                                         dec_ln_b + (size_t)(l * 3 + 2) * Dm);
    }

    // ===================== output projection =====================
    gemm(y, out_w, out_b, out, MR, Vv, Dm, 0);
}

// round 2
// speedup vs baseline: 1.5018x; 1.5018x over previous
#include <cuda_runtime.h>
#include <cuda_bf16.h>
#include <math.h>

#define Dm   512
#define Hh   8
#define DKh  64
#define FFm  2048
#define Vv   10000
#define Ll   6
#define Bb   8
#define Ss   512
#define MR   (Bb*Ss)   // 4096 token rows

// ---------------- scratch (device globals; no allocation allowed) ----------
__device__ float g_x [MR*Dm];
__device__ float g_y [MR*Dm];
__device__ float g_q [MR*Dm];
__device__ float g_k [MR*Dm];
__device__ float g_v [MR*Dm];
__device__ float g_t [MR*Dm];
__device__ float g_a [MR*Dm];
__device__ float g_ff[MR*FFm];

// ---------------- embedding + sinusoidal positional encoding ---------------
__global__ void embed_kernel(const int* __restrict__ tok,
                             const float* __restrict__ emb,
                             float* __restrict__ x)
{
    int idx = blockIdx.x * blockDim.x + threadIdx.x;
    if (idx >= MR * Dm) return;
    int d  = idx & (Dm - 1);
    int bs = idx >> 9;
    int s  = bs & (Ss - 1);
    int t  = tok[bs];
    const float c = -0.017988946039015985f;  // -ln(10000)/512
    int i2 = d & ~1;
    float f   = expf((float)i2 * c);
    float ang = (float)s * f;
    float pe  = (d & 1) ? cosf(ang) : sinf(ang);
    x[idx] = emb[t * Dm + d] + pe;
}

// ---------------- tensor-core GEMM: C = A[M,K] @ W[K,N] + bias, opt ReLU ---
// bf16 hi/lo split (3 MMA passes) for ~fp32 accuracy.
// BM=BN=128, BK=32, 256 threads (8 warps, 2x4), warp tile 64x32.
#define APAD 40    // smem A row stride in bf16 elems (32 + 8)
#define BPAD 136   // smem B row stride in bf16 elems (128 + 8)

__global__ __launch_bounds__(256, 2)
void tc_gemm_kernel(const float* __restrict__ A,
                    const float* __restrict__ W,
                    const float* __restrict__ bias,
                    float* __restrict__ C,
                    int M, int N, int K, int relu)
{
    __shared__ unsigned short sAhi[128][APAD];
    __shared__ unsigned short sAlo[128][APAD];
    __shared__ unsigned short sBhi[32][BPAD];
    __shared__ unsigned short sBlo[32][BPAD];

    const int tid  = threadIdx.x;
    const int warp = tid >> 5;
    const int lane = tid & 31;
    const int wm   = warp >> 2;          // 0..1
    const int wn   = warp & 3;           // 0..3
    const int g    = lane >> 2;          // 0..7
    const int tg   = lane & 3;           // 0..3

    const int rowBase = blockIdx.y * 128;
    const int colBase = blockIdx.x * 128;
    const int mbase = wm * 64;
    const int nbase = wn * 32;

    float acc[4][4][4];
    #pragma unroll
    for (int i = 0; i < 4; i++)
        #pragma unroll
        for (int j = 0; j < 4; j++)
            #pragma unroll
            for (int e = 0; e < 4; e++) acc[i][j][e] = 0.f;

    const bool nFull = (colBase + 128 <= N);

    for (int k0 = 0; k0 < K; k0 += 32) {
        // ---- load A tile 128x32 fp32 -> hi/lo bf16 smem ----
        #pragma unroll
        for (int i = 0; i < 4; i++) {
            int lin = tid + 256 * i;          // 0..1023 float4s
            int row = lin >> 3;
            int c4  = lin & 7;
            float4 v = *reinterpret_cast<const float4*>(
                &A[(size_t)(rowBase + row) * K + k0 + c4 * 4]);
            float vv[4] = {v.x, v.y, v.z, v.w};
            #pragma unroll
            for (int j = 0; j < 4; j++) {
                __nv_bfloat16 hi = __float2bfloat16_rn(vv[j]);
                float lof = vv[j] - __bfloat162float(hi);
                __nv_bfloat16 lo = __float2bfloat16_rn(lof);
                sAhi[row][c4 * 4 + j] = __bfloat16_as_ushort(hi);
                sAlo[row][c4 * 4 + j] = __bfloat16_as_ushort(lo);
            }
        }
        // ---- load B tile 32x128 fp32 -> hi/lo bf16 smem ----
        #pragma unroll
        for (int i = 0; i < 4; i++) {
            int lin = tid + 256 * i;
            int kr  = lin >> 5;
            int c4  = lin & 31;
            int gcol = colBase + c4 * 4;
            float vv[4];
            if (nFull) {
                float4 v = *reinterpret_cast<const float4*>(
                    &W[(size_t)(k0 + kr) * N + gcol]);
                vv[0] = v.x; vv[1] = v.y; vv[2] = v.z; vv[3] = v.w;
            } else {
                #pragma unroll
                for (int j = 0; j < 4; j++)
                    vv[j] = (gcol + j < N) ? W[(size_t)(k0 + kr) * N + gcol + j] : 0.f;
            }
            #pragma unroll
            for (int j = 0; j < 4; j++) {
                __nv_bfloat16 hi = __float2bfloat16_rn(vv[j]);
                float lof = vv[j] - __bfloat162float(hi);
                __nv_bfloat16 lo = __float2bfloat16_rn(lof);
                sBhi[kr][c4 * 4 + j] = __bfloat16_as_ushort(hi);
                sBlo[kr][c4 * 4 + j] = __bfloat16_as_ushort(lo);
            }
        }
        __syncthreads();

        // ---- 3 passes: Ah*Bh, Ah*Bl, Al*Bh ----
        #pragma unroll
        for (int pass = 0; pass < 3; pass++) {
            const unsigned short (*pA)[APAD] = (pass == 2) ? sAlo : sAhi;
            const unsigned short (*pB)[BPAD] = (pass == 1) ? sBlo : sBhi;

            #pragma unroll
            for (int kk = 0; kk < 32; kk += 16) {
                unsigned int afr[4][4];
                #pragma unroll
                for (int mt = 0; mt < 4; mt++) {
                    int r0 = mbase + mt * 16 + g;
                    int r1 = r0 + 8;
                    int c  = kk + 2 * tg;
                    afr[mt][0] = *reinterpret_cast<const unsigned int*>(&pA[r0][c]);
                    afr[mt][1] = *reinterpret_cast<const unsigned int*>(&pA[r1][c]);
                    afr[mt][2] = *reinterpret_cast<const unsigned int*>(&pA[r0][c + 8]);
                    afr[mt][3] = *reinterpret_cast<const unsigned int*>(&pA[r1][c + 8]);
                }
                unsigned int bfr[4][2];
                #pragma unroll
                for (int nt = 0; nt < 4; nt++) {
                    int n = nbase + nt * 8 + g;
                    int kA = kk + 2 * tg;
                    unsigned int u0 = pB[kA][n];
                    unsigned int u1 = pB[kA + 1][n];
                    bfr[nt][0] = u0 | (u1 << 16);
                    unsigned int u2 = pB[kA + 8][n];
                    unsigned int u3 = pB[kA + 9][n];
                    bfr[nt][1] = u2 | (u3 << 16);
                }
                #pragma unroll
                for (int mt = 0; mt < 4; mt++)
                    #pragma unroll
                    for (int nt = 0; nt < 4; nt++) {
                        asm volatile(
                            "mma.sync.aligned.m16n8k16.row.col.f32.bf16.bf16.f32 "
                            "{%0,%1,%2,%3},{%4,%5,%6,%7},{%8,%9},{%0,%1,%2,%3};\n"
                            : "+f"(acc[mt][nt][0]), "+f"(acc[mt][nt][1]),
                              "+f"(acc[mt][nt][2]), "+f"(acc[mt][nt][3])
                            : "r"(afr[mt][0]), "r"(afr[mt][1]),
                              "r"(afr[mt][2]), "r"(afr[mt][3]),
                              "r"(bfr[nt][0]), "r"(bfr[nt][1]));
                    }
            }
        }
        __syncthreads();
    }

    // ---- epilogue: bias (+relu), guarded on N ----
    #pragma unroll
    for (int mt = 0; mt < 4; mt++) {
        int r0 = rowBase + mbase + mt * 16 + g;
        #pragma unroll
        for (int nt = 0; nt < 4; nt++) {
            int c0 = colBase + nbase + nt * 8 + 2 * tg;
            #pragma unroll
            for (int e = 0; e < 4; e++) {
                int r = r0 + ((e >= 2) ? 8 : 0);
                int c = c0 + (e & 1);
                if (c < N) {
                    float v = acc[mt][nt][e] + bias[c];
                    if (relu) v = fmaxf(v, 0.f);
                    C[(size_t)r * N + c] = v;
                }
            }
        }
    }
}

// ---------------- fused attention (unchanged from R1) ----------------------
__global__ void attn_kernel(const float* __restrict__ Q,
                            const float* __restrict__ Kp,
                            const float* __restrict__ Vp,
                            float* __restrict__ O,
                            const int* __restrict__ mask_tok,
                            int causal)
{
    int q0 = blockIdx.x * 8;
    int h  = blockIdx.y;
    int b  = blockIdx.z;
    int tid = threadIdx.x;

    __shared__ float sQ[8][64];
    __shared__ float sT[32][65];
    __shared__ float sS[8][512];

    for (int i = tid; i < 8 * 64; i += 128) {
        int r = i >> 6, c = i & 63;
        sQ[r][c] = Q[((b * Ss + q0 + r) * Dm) + h * 64 + c];
    }

    for (int kt = 0; kt < 16; kt++) {
        __syncthreads();
        for (int i = tid; i < 32 * 64; i += 128) {
            int r = i >> 6, c = i & 63;
            sT[r][c] = Kp[((b * Ss + kt * 32 + r) * Dm) + h * 64 + c];
        }
        __syncthreads();
        #pragma unroll
        for (int ii = 0; ii < 2; ii++) {
            int e = tid + 128 * ii;
            int kr = e & 31, qr = e >> 5;
            float s = 0.f;
            #pragma unroll
            for (int c = 0; c < 64; c++) s += sQ[qr][c] * sT[kr][c];
            int kg = kt * 32 + kr;
            bool valid = causal ? (kg <= q0 + qr) : (mask_tok[b * Ss + kg] != 0);
            sS[qr][kg] = valid ? s * 0.125f : -INFINITY;
        }
    }
    __syncthreads();

    int warp = tid >> 5, lane = tid & 31;
    for (int r = warp * 2; r < warp * 2 + 2; r++) {
        float m = -INFINITY;
        for (int k = lane; k < 512; k += 32) m = fmaxf(m, sS[r][k]);
        #pragma unroll
        for (int o = 16; o; o >>= 1) m = fmaxf(m, __shfl_xor_sync(0xffffffff, m, o));
        float ssum = 0.f;
        for (int k = lane; k < 512; k += 32) {
            float e = expf(sS[r][k] - m);
            sS[r][k] = e;
            ssum += e;
        }
        #pragma unroll
        for (int o = 16; o; o >>= 1) ssum += __shfl_xor_sync(0xffffffff, ssum, o);
        float inv = (ssum > 0.f) ? (1.f / ssum) : 0.f;
        for (int k = lane; k < 512; k += 32) sS[r][k] *= inv;
    }

    float acc[4] = {0.f, 0.f, 0.f, 0.f};
    for (int vt = 0; vt < 16; vt++) {
        __syncthreads();
        for (int i = tid; i < 32 * 64; i += 128) {
            int r = i >> 6, c = i & 63;
            sT[r][c] = Vp[((b * Ss + vt * 32 + r) * Dm) + h * 64 + c];
        }
        __syncthreads();
        #pragma unroll
        for (int ii = 0; ii < 4; ii++) {
            int e = tid + 128 * ii;
            int qr = e >> 6, c = e & 63;
            float a = acc[ii];
            #pragma unroll
            for (int kr = 0; kr < 32; kr++) a += sS[qr][vt * 32 + kr] * sT[kr][c];
            acc[ii] = a;
        }
    }
    #pragma unroll
    for (int ii = 0; ii < 4; ii++) {
        int e = tid + 128 * ii;
        int qr = e >> 6, c = e & 63;
        O[((b * Ss + q0 + qr) * Dm) + h * 64 + c] = acc[ii];
    }
}

// ---------------- residual + LayerNorm (in-place on x) ---------------------
__global__ void ln_res_kernel(float* __restrict__ x,
                              const float* __restrict__ a,
                              const float* __restrict__ g,
                              const float* __restrict__ b)
{
    int row = blockIdx.x;
    int tid = threadIdx.x;
    __shared__ float red[256];

    float v0 = x[row * Dm + tid]       + a[row * Dm + tid];
    float v1 = x[row * Dm + tid + 256] + a[row * Dm + tid + 256];

    red[tid] = v0 + v1;
    __syncthreads();
    for (int st = 128; st > 0; st >>= 1) {
        if (tid < st) red[tid] += red[tid + st];
        __syncthreads();
    }
    float mu = red[0] * (1.f / 512.f);
    __syncthreads();

    float d0 = v0 - mu, d1 = v1 - mu;
    red[tid] = d0 * d0 + d1 * d1;
    __syncthreads();
    for (int st = 128; st > 0; st >>= 1) {
        if (tid < st) red[tid] += red[tid + st];
        __syncthreads();
    }
    float rs = rsqrtf(red[0] * (1.f / 512.f) + 1e-5f);

    x[row * Dm + tid]       = d0 * rs * g[tid]       + b[tid];
    x[row * Dm + tid + 256] = d1 * rs * g[tid + 256] + b[tid + 256];
}

// ---------------- host orchestration ---------------------------------------
static inline void gemm(const float* A, const float* W, const float* bias,
                        float* C, int M, int N, int K, int relu)
{
    dim3 grid((N + 127) / 128, (M + 127) / 128);
    tc_gemm_kernel<<<grid, 256>>>(A, W, bias, C, M, N, K, relu);
}

extern "C" void kernel_launch(void* const* d_in, const int* in_sizes, int n_in,
                              void* d_out, int out_size)
{
    const int*   src       = (const int*)  d_in[0];
    const int*   tgt       = (const int*)  d_in[1];
    const float* src_emb   = (const float*)d_in[2];
    const float* tgt_emb   = (const float*)d_in[3];
    const float* enc_w     = (const float*)d_in[4];
    const float* enc_b     = (const float*)d_in[5];
    const float* enc_ff1_w = (const float*)d_in[6];
    const float* enc_ff1_b = (const float*)d_in[7];
    const float* enc_ff2_w = (const float*)d_in[8];
    const float* enc_ff2_b = (const float*)d_in[9];
    const float* enc_ln_g  = (const float*)d_in[10];
    const float* enc_ln_b  = (const float*)d_in[11];
    const float* dec_sa_w  = (const float*)d_in[12];
    const float* dec_sa_b  = (const float*)d_in[13];
    const float* dec_ca_w  = (const float*)d_in[14];
    const float* dec_ca_b  = (const float*)d_in[15];
    const float* dec_ff1_w = (const float*)d_in[16];
    const float* dec_ff1_b = (const float*)d_in[17];
    const float* dec_ff2_w = (const float*)d_in[18];
    const float* dec_ff2_b = (const float*)d_in[19];
    const float* dec_ln_g  = (const float*)d_in[20];
    const float* dec_ln_b  = (const float*)d_in[21];
    const float* out_w     = (const float*)d_in[22];
    const float* out_b     = (const float*)d_in[23];
    float* out = (float*)d_out;

    float *x, *y, *q, *k, *v, *t, *a, *ff;
    cudaGetSymbolAddress((void**)&x,  g_x);
    cudaGetSymbolAddress((void**)&y,  g_y);
    cudaGetSymbolAddress((void**)&q,  g_q);
    cudaGetSymbolAddress((void**)&k,  g_k);
    cudaGetSymbolAddress((void**)&v,  g_v);
    cudaGetSymbolAddress((void**)&t,  g_t);
    cudaGetSymbolAddress((void**)&a,  g_a);
    cudaGetSymbolAddress((void**)&ff, g_ff);

    const int DD = Dm * Dm;
    dim3 attn_grid(Ss / 8, Hh, Bb);

    // ===================== encoder =====================
    embed_kernel<<<(MR * Dm + 255) / 256, 256>>>(src, src_emb, x);
    for (int l = 0; l < Ll; l++) {
        const float* w = enc_w + (size_t)l * 4 * DD;
        const float* bb = enc_b + (size_t)l * 4 * Dm;
        gemm(x, w + 0 * DD, bb + 0 * Dm, q, MR, Dm, Dm, 0);
        gemm(x, w + 1 * DD, bb + 1 * Dm, k, MR, Dm, Dm, 0);
        gemm(x, w + 2 * DD, bb + 2 * Dm, v, MR, Dm, Dm, 0);
        attn_kernel<<<attn_grid, 128>>>(q, k, v, t, src, 0);
        gemm(t, w + 3 * DD, bb + 3 * Dm, a, MR, Dm, Dm, 0);
        ln_res_kernel<<<MR, 256>>>(x, a, enc_ln_g + (size_t)(l * 2 + 0) * Dm,
                                         enc_ln_b + (size_t)(l * 2 + 0) * Dm);
        gemm(x, enc_ff1_w + (size_t)l * Dm * FFm, enc_ff1_b + (size_t)l * FFm,
             ff, MR, FFm, Dm, 1);
        gemm(ff, enc_ff2_w + (size_t)l * FFm * Dm, enc_ff2_b + (size_t)l * Dm,
             a, MR, Dm, FFm, 0);
        ln_res_kernel<<<MR, 256>>>(x, a, enc_ln_g + (size_t)(l * 2 + 1) * Dm,
                                         enc_ln_b + (size_t)(l * 2 + 1) * Dm);
    }

    // ===================== decoder =====================
    embed_kernel<<<(MR * Dm + 255) / 256, 256>>>(tgt, tgt_emb, y);
    for (int l = 0; l < Ll; l++) {
        const float* w = dec_sa_w + (size_t)l * 4 * DD;
        const float* bb = dec_sa_b + (size_t)l * 4 * Dm;
        gemm(y, w + 0 * DD, bb + 0 * Dm, q, MR, Dm, Dm, 0);
        gemm(y, w + 1 * DD, bb + 1 * Dm, k, MR, Dm, Dm, 0);
        gemm(y, w + 2 * DD, bb + 2 * Dm, v, MR, Dm, Dm, 0);
        attn_kernel<<<attn_grid, 128>>>(q, k, v, t, (const int*)0, 1);
        gemm(t, w + 3 * DD, bb + 3 * Dm, a, MR, Dm, Dm, 0);
        ln_res_kernel<<<MR, 256>>>(y, a, dec_ln_g + (size_t)(l * 3 + 0) * Dm,
                                         dec_ln_b + (size_t)(l * 3 + 0) * Dm);
        const float* wc = dec_ca_w + (size_t)l * 4 * DD;
        const float* bc = dec_ca_b + (size_t)l * 4 * Dm;
        gemm(y, wc + 0 * DD, bc + 0 * Dm, q, MR, Dm, Dm, 0);
        gemm(x, wc + 1 * DD, bc + 1 * Dm, k, MR, Dm, Dm, 0);
        gemm(x, wc + 2 * DD, bc + 2 * Dm, v, MR, Dm, Dm, 0);
        attn_kernel<<<attn_grid, 128>>>(q, k, v, t, tgt, 0);
        gemm(t, wc + 3 * DD, bc + 3 * Dm, a, MR, Dm, Dm, 0);
        ln_res_kernel<<<MR, 256>>>(y, a, dec_ln_g + (size_t)(l * 3 + 1) * Dm,
                                         dec_ln_b + (size_t)(l * 3 + 1) * Dm);
        gemm(y, dec_ff1_w + (size_t)l * Dm * FFm, dec_ff1_b + (size_t)l * FFm,
             ff, MR, FFm, Dm, 1);
        gemm(ff, dec_ff2_w + (size_t)l * FFm * Dm, dec_ff2_b + (size_t)l * Dm,
             a, MR, Dm, FFm, 0);
        ln_res_kernel<<<MR, 256>>>(y, a, dec_ln_g + (size_t)(l * 3 + 2) * Dm,
                                         dec_ln_b + (size_t)(l * 3 + 2) * Dm);
    }

    // ===================== output projection =====================
    gemm(y, out_w, out_b, out, MR, Vv, Dm, 0);
}

// round 3
// speedup vs baseline: 1.9512x; 1.2993x over previous
#include <cuda_runtime.h>
#include <cuda_bf16.h>
#include <math.h>

#define Dm   512
#define Hh   8
#define FFm  2048
#define Vv   10000
#define Ll   6
#define Bb   8
#define Ss   512
#define MR   (Bb*Ss)          // 4096 token rows
#define QKVS 1536             // fused qkv row stride

typedef __nv_bfloat16 bf;

// ---------------- weight pool offsets (elements), bf16 hi/lo, [N][K] layout -
#define DD_   (512*512)
#define DFF_  (512*2048)
#define OFF_ENC_W   0
#define OFF_ENC_F1  (OFF_ENC_W  + 6*4*DD_)
#define OFF_ENC_F2  (OFF_ENC_F1 + 6*DFF_)
#define OFF_DEC_SA  (OFF_ENC_F2 + 6*DFF_)
#define OFF_DEC_CA  (OFF_DEC_SA + 6*4*DD_)
#define OFF_DEC_F1  (OFF_DEC_CA + 6*4*DD_)
#define OFF_DEC_F2  (OFF_DEC_F1 + 6*DFF_)
#define OFF_OUT     (OFF_DEC_F2 + 6*DFF_)
#define WTOT        (OFF_OUT + 512*10000)

__device__ bf g_whi[WTOT];
__device__ bf g_wlo[WTOT];

// ---------------- activation scratch ---------------------------------------
__device__ float g_x  [MR*Dm];
__device__ float g_y  [MR*Dm];
__device__ float g_a  [MR*Dm];
__device__ float g_qkv[MR*QKVS];
__device__ bf g_xhi[MR*Dm],  g_xlo[MR*Dm];
__device__ bf g_yhi[MR*Dm],  g_ylo[MR*Dm];
__device__ bf g_thi[MR*Dm],  g_tlo[MR*Dm];
__device__ bf g_fhi[MR*FFm], g_flo[MR*FFm];

// ---------------- weight convert + transpose: W[K][N] fp32 -> Wt[N][K] hi/lo
__global__ void convw_kernel(const float* __restrict__ W,
                             bf* __restrict__ hi, bf* __restrict__ lo,
                             int K, int N)
{
    __shared__ float t[32][33];
    int mat = blockIdx.z;
    const float* Wm = W + (size_t)mat * K * N;
    bf* him = hi + (size_t)mat * K * N;
    bf* lom = lo + (size_t)mat * K * N;
    int n0 = blockIdx.x * 32, k0 = blockIdx.y * 32;
    int tx = threadIdx.x, ty = threadIdx.y;    // 32 x 8
    #pragma unroll
    for (int j = 0; j < 32; j += 8) {
        int n = n0 + tx;
        t[ty + j][tx] = (n < N) ? Wm[(size_t)(k0 + ty + j) * N + n] : 0.f;
    }
    __syncthreads();
    #pragma unroll
    for (int j = 0; j < 32; j += 8) {
        int n = n0 + ty + j, k = k0 + tx;
        if (n < N) {
            float v = t[tx][ty + j];
            bf h = __float2bfloat16_rn(v);
            him[(size_t)n * K + k] = h;
            lom[(size_t)n * K + k] = __float2bfloat16_rn(v - __bfloat162float(h));
        }
    }
}

// ---------------- embedding + posenc, emits fp32 + hi/lo -------------------
__global__ void embed_kernel(const int* __restrict__ tok,
                             const float* __restrict__ emb,
                             float* __restrict__ x,
                             bf* __restrict__ xhi, bf* __restrict__ xlo)
{
    int idx = blockIdx.x * blockDim.x + threadIdx.x;
    if (idx >= MR * Dm) return;
    int d  = idx & (Dm - 1);
    int bs = idx >> 9;
    int s  = bs & (Ss - 1);
    int t  = tok[bs];
    const float c = -0.017988946039015985f;  // -ln(10000)/512
    int i2 = d & ~1;
    float f   = expf((float)i2 * c);
    float ang = (float)s * f;
    float pe  = (d & 1) ? cosf(ang) : sinf(ang);
    float v = emb[t * Dm + d] + pe;
    x[idx] = v;
    bf h = __float2bfloat16_rn(v);
    xhi[idx] = h;
    xlo[idx] = __float2bfloat16_rn(v - __bfloat162float(h));
}

// ---------------- bf16 hi/lo 3-pass tensor-core GEMM -----------------------
// A[M][K] split (Ahi,Alo); W transposed [N][K] split (Whi,Wlo).
// C = A*W^T(+bias)(+relu). mode 0: fp32 out; mode 1: relu + hi/lo out.
// MT = m16-tiles per warp (4 -> warp 64x64, 2 -> warp 32x64).
// WM = warps along M. 8 warps total. BN = (8/WM)*64.
#define MMA_BF16(acc, a, b)                                            \
    asm volatile(                                                      \
        "mma.sync.aligned.m16n8k16.row.col.f32.bf16.bf16.f32 "         \
        "{%0,%1,%2,%3},{%4,%5,%6,%7},{%8,%9},{%0,%1,%2,%3};\n"         \
        : "+f"((acc)[0]), "+f"((acc)[1]), "+f"((acc)[2]), "+f"((acc)[3])\
        : "r"((a)[0]), "r"((a)[1]), "r"((a)[2]), "r"((a)[3]),          \
          "r"((b)[0]), "r"((b)[1]))

template<int MT, int WM>
__global__ void __launch_bounds__(256, (MT == 2) ? 2 : 1)
gemm3_kernel(const bf* __restrict__ Ahi, const bf* __restrict__ Alo,
             const bf* __restrict__ Whi, const bf* __restrict__ Wlo,
             const float* __restrict__ bias,
             int K, int Ncols, int ldc, int cOff, int mode,
             float* __restrict__ Cf, bf* __restrict__ Chi, bf* __restrict__ Clo)
{
    constexpr int WNW   = 8 / WM;
    constexpr int BN    = WNW * 64;
    constexpr int AS    = 128 * 40;         // halves per A sub-tile
    constexpr int BS    = BN * 40;
    constexpr int STAGE = 2 * AS + 2 * BS;  // halves per stage
    extern __shared__ unsigned short sh[];

    const int tid  = threadIdx.x;
    const int warp = tid >> 5, lane = tid & 31;
    const int g    = lane >> 2, tg = lane & 3;
    const int wm   = warp % WM, wn = warp / WM;
    const int mbase = wm * (MT * 16);
    const int nbase = wn * 64;
    const int rowBase = blockIdx.y * 128;
    const int colBase = blockIdx.x * BN;

    float acc[MT][8][4];
    #pragma unroll
    for (int mt = 0; mt < MT; mt++)
        #pragma unroll
        for (int nt = 0; nt < 8; nt++)
            #pragma unroll
            for (int e = 0; e < 4; e++) acc[mt][nt][e] = 0.f;

    const int KT = K >> 5;

    auto loadStage = [&](int kt, int s) {
        const int k0 = kt << 5;
        unsigned short* sAh = sh + s * STAGE;
        unsigned short* sAl = sAh + AS;
        unsigned short* sBh = sAl + AS;
        unsigned short* sBl = sBh + BS;
        #pragma unroll
        for (int i = 0; i < 4; i++) {                 // 1024 A chunks
            int id  = tid + 256 * i;
            int arr = id >> 9, r = (id >> 2) & 127, cc = id & 3;
            const bf* src = (arr ? Alo : Ahi) + (size_t)(rowBase + r) * K + k0 + cc * 8;
            unsigned u = (unsigned)__cvta_generic_to_shared(
                (arr ? sAl : sAh) + r * 40 + cc * 8);
            asm volatile("cp.async.cg.shared.global [%0], [%1], 16;\n"
                         :: "r"(u), "l"(src));
        }
        #pragma unroll
        for (int i = 0; i < BN / 32; i++) {           // BN*8 B chunks
            int id  = tid + 256 * i;
            int arr = (id >= BN * 4);
            int t   = id - arr * BN * 4;
            int r   = t >> 2, cc = t & 3;
            int n   = colBase + r;
            int v   = (n < Ncols) ? 16 : 0;
            const bf* src = (arr ? Wlo : Whi) + (size_t)(v ? n : 0) * K + k0 + cc * 8;
            unsigned u = (unsigned)__cvta_generic_to_shared(
                (arr ? sBl : sBh) + r * 40 + cc * 8);
            asm volatile("cp.async.cg.shared.global [%0], [%1], 16, %2;\n"
                         :: "r"(u), "l"(src), "r"(v));
        }
        asm volatile("cp.async.commit_group;\n");
    };

    auto computeStage = [&](int s) {
        const unsigned short* sAh = sh + s * STAGE;
        const unsigned short* sAl = sAh + AS;
        const unsigned short* sBh = sAl + AS;
        const unsigned short* sBl = sBh + BS;
        #pragma unroll
        for (int kk = 0; kk < 32; kk += 16) {
            unsigned ah[MT][4], bh[8][2];
            #pragma unroll
            for (int mt = 0; mt < MT; mt++) {
                const unsigned short* p = sAh + (mbase + mt * 16 + g) * 40 + kk + 2 * tg;
                ah[mt][0] = *(const unsigned*)(p);
                ah[mt][1] = *(const unsigned*)(p + 320);
                ah[mt][2] = *(const unsigned*)(p + 8);
                ah[mt][3] = *(const unsigned*)(p + 328);
            }
            #pragma unroll
            for (int nt = 0; nt < 8; nt++) {
                const unsigned short* p = sBh + (nbase + nt * 8 + g) * 40 + kk + 2 * tg;
                bh[nt][0] = *(const unsigned*)(p);
                bh[nt][1] = *(const unsigned*)(p + 8);
            }
            #pragma unroll
            for (int mt = 0; mt < MT; mt++)
                #pragma unroll
                for (int nt = 0; nt < 8; nt++)
                    MMA_BF16(acc[mt][nt], ah[mt], bh[nt]);
            {
                unsigned bl[8][2];
                #pragma unroll
                for (int nt = 0; nt < 8; nt++) {
                    const unsigned short* p = sBl + (nbase + nt * 8 + g) * 40 + kk + 2 * tg;
                    bl[nt][0] = *(const unsigned*)(p);
                    bl[nt][1] = *(const unsigned*)(p + 8);
                }
                #pragma unroll
                for (int mt = 0; mt < MT; mt++)
                    #pragma unroll
                    for (int nt = 0; nt < 8; nt++)
                        MMA_BF16(acc[mt][nt], ah[mt], bl[nt]);
            }
            {
                unsigned al[MT][4];
                #pragma unroll
                for (int mt = 0; mt < MT; mt++) {
                    const unsigned short* p = sAl + (mbase + mt * 16 + g) * 40 + kk + 2 * tg;
                    al[mt][0] = *(const unsigned*)(p);
                    al[mt][1] = *(const unsigned*)(p + 320);
                    al[mt][2] = *(const unsigned*)(p + 8);
                    al[mt][3] = *(const unsigned*)(p + 328);
                }
                #pragma unroll
                for (int mt = 0; mt < MT; mt++)
                    #pragma unroll
                    for (int nt = 0; nt < 8; nt++)
                        MMA_BF16(acc[mt][nt], al[mt], bh[nt]);
            }
        }
    };

    loadStage(0, 0);
    for (int kt = 0; kt < KT; kt++) {
        if (kt + 1 < KT) {
            loadStage(kt + 1, (kt + 1) & 1);
            asm volatile("cp.async.wait_group 1;\n");
        } else {
            asm volatile("cp.async.wait_group 0;\n");
        }
        __syncthreads();
        computeStage(kt & 1);
        __syncthreads();
    }

    #pragma unroll
    for (int mt = 0; mt < MT; mt++) {
        int r0 = rowBase + mbase + mt * 16 + g;
        #pragma unroll
        for (int nt = 0; nt < 8; nt++) {
            int nloc = colBase + nbase + nt * 8 + 2 * tg;
            #pragma unroll
            for (int e = 0; e < 4; e++) {
                int r = r0 + ((e >= 2) ? 8 : 0);
                int n = nloc + (e & 1);
                if (n < Ncols) {
                    float v = acc[mt][nt][e] + bias[n];
                    size_t o = (size_t)r * ldc + cOff + n;
                    if (mode == 1) {
                        v = fmaxf(v, 0.f);
                        bf h = __float2bfloat16_rn(v);
                        Chi[o] = h;
                        Clo[o] = __float2bfloat16_rn(v - __bfloat162float(h));
                    } else {
                        Cf[o] = v;
                    }
                }
            }
        }
    }
}

// ---------------- fused attention: reads packed qkv[MR][1536], writes hi/lo -
__global__ void attn_kernel(const float* __restrict__ QKV,
                            bf* __restrict__ Ohi, bf* __restrict__ Olo,
                            const int* __restrict__ mask_tok,
                            int causal)
{
    int q0 = blockIdx.x * 8;
    int h  = blockIdx.y;
    int b  = blockIdx.z;
    int tid = threadIdx.x;

    __shared__ float sQ[8][64];
    __shared__ float sT[32][65];
    __shared__ float sS[8][512];

    const float* Qp = QKV + h * 64;
    const float* Kp = QKV + 512 + h * 64;
    const float* Vp = QKV + 1024 + h * 64;

    for (int i = tid; i < 8 * 64; i += 128) {
        int r = i >> 6, c = i & 63;
        sQ[r][c] = Qp[(size_t)(b * Ss + q0 + r) * QKVS + c];
    }

    for (int kt = 0; kt < 16; kt++) {
        __syncthreads();
        for (int i = tid; i < 32 * 64; i += 128) {
            int r = i >> 6, c = i & 63;
            sT[r][c] = Kp[(size_t)(b * Ss + kt * 32 + r) * QKVS + c];
        }
        __syncthreads();
        #pragma unroll
        for (int ii = 0; ii < 2; ii++) {
            int e = tid + 128 * ii;
            int kr = e & 31, qr = e >> 5;
            float s = 0.f;
            #pragma unroll
            for (int c = 0; c < 64; c++) s += sQ[qr][c] * sT[kr][c];
            int kg = kt * 32 + kr;
            bool valid = causal ? (kg <= q0 + qr) : (mask_tok[b * Ss + kg] != 0);
            sS[qr][kg] = valid ? s * 0.125f : -INFINITY;
        }
    }
    __syncthreads();

    int warp = tid >> 5, lane = tid & 31;
    for (int r = warp * 2; r < warp * 2 + 2; r++) {
        float m = -INFINITY;
        for (int k = lane; k < 512; k += 32) m = fmaxf(m, sS[r][k]);
        #pragma unroll
        for (int o = 16; o; o >>= 1) m = fmaxf(m, __shfl_xor_sync(0xffffffff, m, o));
        float ssum = 0.f;
        for (int k = lane; k < 512; k += 32) {
            float e = expf(sS[r][k] - m);
            sS[r][k] = e;
            ssum += e;
        }
        #pragma unroll
        for (int o = 16; o; o >>= 1) ssum += __shfl_xor_sync(0xffffffff, ssum, o);
        float inv = (ssum > 0.f) ? (1.f / ssum) : 0.f;
        for (int k = lane; k < 512; k += 32) sS[r][k] *= inv;
    }

    float acc[4] = {0.f, 0.f, 0.f, 0.f};
    for (int vt = 0; vt < 16; vt++) {
        __syncthreads();
        for (int i = tid; i < 32 * 64; i += 128) {
            int r = i >> 6, c = i & 63;
            sT[r][c] = Vp[(size_t)(b * Ss + vt * 32 + r) * QKVS + c];
        }
        __syncthreads();
        #pragma unroll
        for (int ii = 0; ii < 4; ii++) {
            int e = tid + 128 * ii;
            int qr = e >> 6, c = e & 63;
            float a = acc[ii];
            #pragma unroll
            for (int kr = 0; kr < 32; kr++) a += sS[qr][vt * 32 + kr] * sT[kr][c];
            acc[ii] = a;
        }
    }
    #pragma unroll
    for (int ii = 0; ii < 4; ii++) {
        int e = tid + 128 * ii;
        int qr = e >> 6, c = e & 63;
        size_t o = (size_t)(b * Ss + q0 + qr) * Dm + h * 64 + c;
        float v = acc[ii];
        bf hv = __float2bfloat16_rn(v);
        Ohi[o] = hv;
        Olo[o] = __float2bfloat16_rn(v - __bfloat162float(hv));
    }
}

// ---------------- residual + LayerNorm, emits fp32 + hi/lo -----------------
__global__ void ln_res_kernel(float* __restrict__ x,
                              const float* __restrict__ a,
                              const float* __restrict__ g,
                              const float* __restrict__ b,
                              bf* __restrict__ xhi, bf* __restrict__ xlo)
{
    int row = blockIdx.x;
    int tid = threadIdx.x;
    __shared__ float red[256];

    float v0 = x[row * Dm + tid]       + a[row * Dm + tid];
    float v1 = x[row * Dm + tid + 256] + a[row * Dm + tid + 256];

    red[tid] = v0 + v1;
    __syncthreads();
    for (int st = 128; st > 0; st >>= 1) {
        if (tid < st) red[tid] += red[tid + st];
        __syncthreads();
    }
    float mu = red[0] * (1.f / 512.f);
    __syncthreads();

    float d0 = v0 - mu, d1 = v1 - mu;
    red[tid] = d0 * d0 + d1 * d1;
    __syncthreads();
    for (int st = 128; st > 0; st >>= 1) {
        if (tid < st) red[tid] += red[tid + st];
        __syncthreads();
    }
    float rs = rsqrtf(red[0] * (1.f / 512.f) + 1e-5f);

    float o0 = d0 * rs * g[tid]       + b[tid];
    float o1 = d1 * rs * g[tid + 256] + b[tid + 256];
    x[row * Dm + tid]       = o0;
    x[row * Dm + tid + 256] = o1;
    bf h0 = __float2bfloat16_rn(o0);
    bf h1 = __float2bfloat16_rn(o1);
    xhi[row * Dm + tid]       = h0;
    xhi[row * Dm + tid + 256] = h1;
    xlo[row * Dm + tid]       = __float2bfloat16_rn(o0 - __bfloat162float(h0));
    xlo[row * Dm + tid + 256] = __float2bfloat16_rn(o1 - __bfloat162float(h1));
}

// ---------------- host side ------------------------------------------------
#define SMEM_BIG   122880   // 2 stages * (2*128*40 + 2*256*40) halves * 2B
#define SMEM_SMALL 81920    // 2 stages * (2*128*40 + 2*128*40) halves * 2B

static void gemm3(const bf* Ahi, const bf* Alo, const bf* Whi, const bf* Wlo,
                  const float* bias, int K, int Ncols, int ldc, int cOff,
                  int mode, float* Cf, bf* Chi, bf* Clo)
{
    if (Ncols >= 1024) {
        dim3 grid((Ncols + 255) / 256, MR / 128);
        gemm3_kernel<4, 2><<<grid, 256, SMEM_BIG>>>(
            Ahi, Alo, Whi, Wlo, bias, K, Ncols, ldc, cOff, mode, Cf, Chi, Clo);
    } else {
        dim3 grid((Ncols + 127) / 128, MR / 128);
        gemm3_kernel<2, 4><<<grid, 256, SMEM_SMALL>>>(
            Ahi, Alo, Whi, Wlo, bias, K, Ncols, ldc, cOff, mode, Cf, Chi, Clo);
    }
}

static void convw(const float* W, bf* hi, bf* lo, size_t off, int K, int N, int nmat)
{
    dim3 grid((N + 31) / 32, K / 32, nmat);
    convw_kernel<<<grid, dim3(32, 8)>>>(W, hi + off, lo + off, K, N);
}

extern "C" void kernel_launch(void* const* d_in, const int* in_sizes, int n_in,
                              void* d_out, int out_size)
{
    const int*   src       = (const int*)  d_in[0];
    const int*   tgt       = (const int*)  d_in[1];
    const float* src_emb   = (const float*)d_in[2];
    const float* tgt_emb   = (const float*)d_in[3];
    const float* enc_w     = (const float*)d_in[4];
    const float* enc_b     = (const float*)d_in[5];
    const float* enc_ff1_w = (const float*)d_in[6];
    const float* enc_ff1_b = (const float*)d_in[7];
    const float* enc_ff2_w = (const float*)d_in[8];
    const float* enc_ff2_b = (const float*)d_in[9];
    const float* enc_ln_g  = (const float*)d_in[10];
    const float* enc_ln_b  = (const float*)d_in[11];
    const float* dec_sa_w  = (const float*)d_in[12];
    const float* dec_sa_b  = (const float*)d_in[13];
    const float* dec_ca_w  = (const float*)d_in[14];
    const float* dec_ca_b  = (const float*)d_in[15];
    const float* dec_ff1_w = (const float*)d_in[16];
    const float* dec_ff1_b = (const float*)d_in[17];
    const float* dec_ff2_w = (const float*)d_in[18];
    const float* dec_ff2_b = (const float*)d_in[19];
    const float* dec_ln_g  = (const float*)d_in[20];
    const float* dec_ln_b  = (const float*)d_in[21];
    const float* out_w     = (const float*)d_in[22];
    const float* out_b     = (const float*)d_in[23];
    float* out = (float*)d_out;

    cudaFuncSetAttribute(gemm3_kernel<4, 2>,
        cudaFuncAttributeMaxDynamicSharedMemorySize, SMEM_BIG);
    cudaFuncSetAttribute(gemm3_kernel<2, 4>,
        cudaFuncAttributeMaxDynamicSharedMemorySize, SMEM_SMALL);

    float *x, *y, *a, *qkv;
    bf *whi, *wlo, *xhi, *xlo, *yhi, *ylo, *thi, *tlo, *fhi, *flo;
    cudaGetSymbolAddress((void**)&x,   g_x);
    cudaGetSymbolAddress((void**)&y,   g_y);
    cudaGetSymbolAddress((void**)&a,   g_a);
    cudaGetSymbolAddress((void**)&qkv, g_qkv);
    cudaGetSymbolAddress((void**)&whi, g_whi);
    cudaGetSymbolAddress((void**)&wlo, g_wlo);
    cudaGetSymbolAddress((void**)&xhi, g_xhi);
    cudaGetSymbolAddress((void**)&xlo, g_xlo);
    cudaGetSymbolAddress((void**)&yhi, g_yhi);
    cudaGetSymbolAddress((void**)&ylo, g_ylo);
    cudaGetSymbolAddress((void**)&thi, g_thi);
    cudaGetSymbolAddress((void**)&tlo, g_tlo);
    cudaGetSymbolAddress((void**)&fhi, g_fhi);
    cudaGetSymbolAddress((void**)&flo, g_flo);

    // ---- weight conversion (transpose + hi/lo split) ----
    convw(enc_w,     whi, wlo, OFF_ENC_W,  512, 512,  24);
    convw(enc_ff1_w, whi, wlo, OFF_ENC_F1, 512, 2048, 6);
    convw(enc_ff2_w, whi, wlo, OFF_ENC_F2, 2048, 512, 6);
    convw(dec_sa_w,  whi, wlo, OFF_DEC_SA, 512, 512,  24);
    convw(dec_ca_w,  whi, wlo, OFF_DEC_CA, 512, 512,  24);
    convw(dec_ff1_w, whi, wlo, OFF_DEC_F1, 512, 2048, 6);
    convw(dec_ff2_w, whi, wlo, OFF_DEC_F2, 2048, 512, 6);
    convw(out_w,     whi, wlo, OFF_OUT,    512, 10000, 1);

    dim3 attn_grid(Ss / 8, Hh, Bb);

    // ===================== encoder =====================
    embed_kernel<<<(MR * Dm + 255) / 256, 256>>>(src, src_emb, x, xhi, xlo);
    for (int l = 0; l < Ll; l++) {
        size_t wo = OFF_ENC_W + (size_t)l * 4 * DD_;
        const float* bb = enc_b + (size_t)l * 4 * Dm;
        gemm3(xhi, xlo, whi + wo, wlo + wo, bb,
              512, 1536, QKVS, 0, 0, qkv, 0, 0);
        attn_kernel<<<attn_grid, 128>>>(qkv, thi, tlo, src, 0);
        gemm3(thi, tlo, whi + wo + 3 * DD_, wlo + wo + 3 * DD_, bb + 3 * Dm,
              512, 512, Dm, 0, 0, a, 0, 0);
        ln_res_kernel<<<MR, 256>>>(x, a, enc_ln_g + (size_t)(l * 2 + 0) * Dm,
                                         enc_ln_b + (size_t)(l * 2 + 0) * Dm, xhi, xlo);
        size_t f1 = OFF_ENC_F1 + (size_t)l * DFF_;
        gemm3(xhi, xlo, whi + f1, wlo + f1, enc_ff1_b + (size_t)l * FFm,
              512, 2048, FFm, 0, 1, 0, fhi, flo);
        size_t f2 = OFF_ENC_F2 + (size_t)l * DFF_;
        gemm3(fhi, flo, whi + f2, wlo + f2, enc_ff2_b + (size_t)l * Dm,
              2048, 512, Dm, 0, 0, a, 0, 0);
        ln_res_kernel<<<MR, 256>>>(x, a, enc_ln_g + (size_t)(l * 2 + 1) * Dm,
                                         enc_ln_b + (size_t)(l * 2 + 1) * Dm, xhi, xlo);
    }

    // ===================== decoder =====================
    embed_kernel<<<(MR * Dm + 255) / 256, 256>>>(tgt, tgt_emb, y, yhi, ylo);
    for (int l = 0; l < Ll; l++) {
        // self-attention (causal)
        size_t wo = OFF_DEC_SA + (size_t)l * 4 * DD_;
        const float* bb = dec_sa_b + (size_t)l * 4 * Dm;
        gemm3(yhi, ylo, whi + wo, wlo + wo, bb,
              512, 1536, QKVS, 0, 0, qkv, 0, 0);
        attn_kernel<<<attn_grid, 128>>>(qkv, thi, tlo, (const int*)0, 1);
        gemm3(thi, tlo, whi + wo + 3 * DD_, wlo + wo + 3 * DD_, bb + 3 * Dm,
              512, 512, Dm, 0, 0, a, 0, 0);
        ln_res_kernel<<<MR, 256>>>(y, a, dec_ln_g + (size_t)(l * 3 + 0) * Dm,
                                         dec_ln_b + (size_t)(l * 3 + 0) * Dm, yhi, ylo);
        // cross-attention: Q from y, K/V from enc_out (x)
        size_t wc = OFF_DEC_CA + (size_t)l * 4 * DD_;
        const float* bc = dec_ca_b + (size_t)l * 4 * Dm;
        gemm3(yhi, ylo, whi + wc, wlo + wc, bc,
              512, 512, QKVS, 0, 0, qkv, 0, 0);
        gemm3(xhi, xlo, whi + wc + DD_, wlo + wc + DD_, bc + Dm,
              512, 1024, QKVS, 512, 0, qkv, 0, 0);
        attn_kernel<<<attn_grid, 128>>>(qkv, thi, tlo, tgt, 0);
        gemm3(thi, tlo, whi + wc + 3 * DD_, wlo + wc + 3 * DD_, bc + 3 * Dm,
              512, 512, Dm, 0, 0, a, 0, 0);
        ln_res_kernel<<<MR, 256>>>(y, a, dec_ln_g + (size_t)(l * 3 + 1) * Dm,
                                         dec_ln_b + (size_t)(l * 3 + 1) * Dm, yhi, ylo);
        // FFN
        size_t f1 = OFF_DEC_F1 + (size_t)l * DFF_;
        gemm3(yhi, ylo, whi + f1, wlo + f1, dec_ff1_b + (size_t)l * FFm,
              512, 2048, FFm, 0, 1, 0, fhi, flo);
        size_t f2 = OFF_DEC_F2 + (size_t)l * DFF_;
        gemm3(fhi, flo, whi + f2, wlo + f2, dec_ff2_b + (size_t)l * Dm,
              2048, 512, Dm, 0, 0, a, 0, 0);
        ln_res_kernel<<<MR, 256>>>(y, a, dec_ln_g + (size_t)(l * 3 + 2) * Dm,
                                         dec_ln_b + (size_t)(l * 3 + 2) * Dm, yhi, ylo);
    }

    // ===================== output projection =====================
    gemm3(yhi, ylo, whi + OFF_OUT, wlo + OFF_OUT, out_b,
          512, 10000, Vv, 0, 0, out, 0, 0);
}